// round 2
// baseline (speedup 1.0000x reference)
#include <cuda_runtime.h>
#include <math.h>

#define T_LEN 1024
#define BATCH 64
#define HID   512
#define G4H   2048
#define NBLK  128
#define WS    516                      // padded smem row stride (conflict-free)
#define OUT_ELEMS 67108864LL           // T*B*2H
#define HID_ELEMS 131072LL             // 2L*B*H

// Scratch (allocation-free rule: __device__ globals)
__device__ float g_G[2][134217728];    // [d][T*B][4H]  precomputed x-part + biases
__device__ float g_seq[2][33554432];   // [d][T][B][H]  per-layer sequence output
__device__ float g_h[2][2][32768];     // [pingpong][d][B*H]
__device__ unsigned long long g_bar = 0ull;

__device__ __forceinline__ float sigf(float x){ return 1.0f / (1.0f + expf(-x)); }

// Monotonic-ticket grid barrier: self-consistent across multiple launches,
// never reset, u64 so it cannot overflow over the whole bench.
__device__ __forceinline__ void grid_barrier(){
    __threadfence();
    __syncthreads();
    if (threadIdx.x == 0){
        unsigned long long ticket = atomicAdd(&g_bar, 1ull);
        unsigned long long target = (ticket / NBLK + 1ull) * (unsigned long long)NBLK;
        while (atomicAdd(&g_bar, 0ull) < target) { __nanosleep(64); }
    }
    __syncthreads();
}

__global__ void zero_h_kernel(){
    int idx = blockIdx.x * blockDim.x + threadIdx.x;
    if (idx < 2*2*32768) ((float*)g_h)[idx] = 0.0f;
}

// ---------------------------------------------------------------------------
// Input-projection SGEMM: G[d][m][n] = X[m,:] . W[n,:] + bx[n] + bh[n]
// M=65536, N=2048, K=512. 128x128 block tile, 8x8 thread tile, BK=16.
// ---------------------------------------------------------------------------
__global__ void __launch_bounds__(256, 2)
gemm_kernel(int layer, const float* __restrict__ x,
            const float* __restrict__ Wxf, const float* __restrict__ Wxb,
            const float* __restrict__ bxf, const float* __restrict__ bhf,
            const float* __restrict__ bxb, const float* __restrict__ bhb)
{
    const int d = blockIdx.z;
    const float* X  = (layer == 0) ? x : g_seq[d];
    const float* W  = (d ? Wxb : Wxf) + (size_t)layer * G4H * HID;
    const float* bx = (d ? bxb : bxf) + layer * G4H;
    const float* bh = (d ? bhb : bhf) + layer * G4H;
    float* Gout = g_G[d];

    __shared__ float As[16][132];   // [k][m]
    __shared__ float Bs[16][132];   // [k][n]

    const int tid = threadIdx.x;
    const int tx = tid & 15;
    const int ty = tid >> 4;
    const int m0 = blockIdx.x * 128;
    const int n0 = blockIdx.y * 128;
    const int lrow = tid >> 2;        // 0..63
    const int lk   = (tid & 3) * 4;   // 0,4,8,12

    float acc[8][8];
    #pragma unroll
    for (int i = 0; i < 8; i++)
        #pragma unroll
        for (int j = 0; j < 8; j++) acc[i][j] = 0.0f;

    for (int kt = 0; kt < HID; kt += 16){
        #pragma unroll
        for (int hh = 0; hh < 2; hh++){
            int row = lrow + hh * 64;
            float4 va = *(const float4*)(X + (size_t)(m0 + row) * HID + kt + lk);
            As[lk+0][row] = va.x; As[lk+1][row] = va.y;
            As[lk+2][row] = va.z; As[lk+3][row] = va.w;
            float4 vb = *(const float4*)(W + (size_t)(n0 + row) * HID + kt + lk);
            Bs[lk+0][row] = vb.x; Bs[lk+1][row] = vb.y;
            Bs[lk+2][row] = vb.z; Bs[lk+3][row] = vb.w;
        }
        __syncthreads();
        #pragma unroll
        for (int kk = 0; kk < 16; kk++){
            float a[8], b[8];
            *(float4*)(a)     = *(const float4*)&As[kk][ty*8];
            *(float4*)(a + 4) = *(const float4*)&As[kk][ty*8 + 4];
            *(float4*)(b)     = *(const float4*)&Bs[kk][tx*8];
            *(float4*)(b + 4) = *(const float4*)&Bs[kk][tx*8 + 4];
            #pragma unroll
            for (int i = 0; i < 8; i++)
                #pragma unroll
                for (int j = 0; j < 8; j++)
                    acc[i][j] += a[i] * b[j];
        }
        __syncthreads();
    }

    float bias[8];
    #pragma unroll
    for (int j = 0; j < 8; j++){
        int n = n0 + tx*8 + j;
        bias[j] = bx[n] + bh[n];
    }
    #pragma unroll
    for (int i = 0; i < 8; i++){
        size_t off = (size_t)(m0 + ty*8 + i) * G4H + n0 + tx*8;
        float4 o0 = make_float4(acc[i][0]+bias[0], acc[i][1]+bias[1],
                                acc[i][2]+bias[2], acc[i][3]+bias[3]);
        float4 o1 = make_float4(acc[i][4]+bias[4], acc[i][5]+bias[5],
                                acc[i][6]+bias[6], acc[i][7]+bias[7]);
        *(float4*)(Gout + off)     = o0;
        *(float4*)(Gout + off + 4) = o1;
    }
}

// ---------------------------------------------------------------------------
// Persistent recurrent kernel. grid = 128 (1 block/SM, co-resident).
// Block -> (direction d = bid/64, hidden units j0..j0+7). Wh slice (32 gate
// rows x 512) lives in smem for all 1024 steps; c lives in registers.
// Per step: stage h (64x512) to smem, 4-way k-split GEMM (4x8 reg tiles),
// smem reduction, gate math, grid barrier.
// ---------------------------------------------------------------------------
__global__ void __launch_bounds__(256, 1)
recur_kernel(int layer, const float* __restrict__ Whh_f,
             const float* __restrict__ Whh_b, float* __restrict__ out)
{
    extern __shared__ float sm[];
    float* w_s = sm;                 // 32 * WS
    float* h_s = sm + 32 * WS;       // 64 * WS
    float* buf = h_s;                // alias: 4*32*65 floats used after k-loop

    const int tid = threadIdx.x;
    const int bid = blockIdx.x;
    const int d  = bid >> 6;
    const int j0 = (bid & 63) << 3;
    const float* Wh = (d ? Whh_b : Whh_f) + (size_t)layer * G4H * HID;
    const float* Gm = g_G[d];

    // Load this block's 32 gate rows of Wh once (reused all steps).
    for (int idx = tid; idx < 32 * 512; idx += 256){
        int rr = idx >> 9, k = idx & 511;
        int rg = ((rr >> 3) << 9) + j0 + (rr & 7);   // gate*512 + j0 + jl
        w_s[rr * WS + k] = Wh[(size_t)rg * HID + k];
    }

    // k-split GEMM roles: 4 groups of 64 threads, each group 128 k's.
    const int kg = tid >> 6;
    const int q  = tid & 63;
    const int tc = q & 7;            // b = tc + 8u
    const int tr = q >> 3;           // gate-row = i*8 + tr
    const int kbase = kg << 7;

    // combine roles: out = b*8 + jl (jl fastest -> coalesced G reads)
    const int jl = tid & 7;
    const int b0 = tid >> 3;         // 0..31 ; second output at b0+32
    float c0 = 0.0f, c1 = 0.0f;
    int p = 0;

    for (int s = 0; s < T_LEN; s++){
        const int t = d ? (T_LEN - 1 - s) : s;

        // stage h (bypass L1: written by other SMs between steps)
        const float* hsrc = g_h[p][d];
        #pragma unroll
        for (int it = 0; it < 32; it++){
            int fi = (tid + it * 256) * 4;
            int b = fi >> 9, k = fi & 511;
            float4 v = __ldcg((const float4*)(hsrc + fi));
            *(float4*)&h_s[b * WS + k] = v;
        }
        // prefetch G (DRAM latency hides behind the k-loop)
        const size_t mb0 = ((size_t)t * 64 + b0)      * G4H + j0 + jl;
        const size_t mb1 = ((size_t)t * 64 + b0 + 32) * G4H + j0 + jl;
        float ga0[4], ga1[4];
        #pragma unroll
        for (int e = 0; e < 4; e++){
            ga0[e] = __ldg(Gm + mb0 + (e << 9));
            ga1[e] = __ldg(Gm + mb1 + (e << 9));
        }
        __syncthreads();

        float acc[4][8];
        #pragma unroll
        for (int i = 0; i < 4; i++)
            #pragma unroll
            for (int u = 0; u < 8; u++) acc[i][u] = 0.0f;

        #pragma unroll 4
        for (int kq = 0; kq < 32; kq++){
            const int k = kbase + (kq << 2);
            float4 wv[4], hv[8];
            #pragma unroll
            for (int i = 0; i < 4; i++)
                wv[i] = *(const float4*)&w_s[(i*8 + tr) * WS + k];
            #pragma unroll
            for (int u = 0; u < 8; u++)
                hv[u] = *(const float4*)&h_s[(tc + (u << 3)) * WS + k];
            #pragma unroll
            for (int i = 0; i < 4; i++)
                #pragma unroll
                for (int u = 0; u < 8; u++){
                    acc[i][u] += wv[i].x * hv[u].x;
                    acc[i][u] += wv[i].y * hv[u].y;
                    acc[i][u] += wv[i].z * hv[u].z;
                    acc[i][u] += wv[i].w * hv[u].w;
                }
        }
        __syncthreads();   // everyone done reading h_s before buf alias writes

        #pragma unroll
        for (int i = 0; i < 4; i++)
            #pragma unroll
            for (int u = 0; u < 8; u++)
                buf[(kg*32 + i*8 + tr) * 65 + tc + (u << 3)] = acc[i][u];
        __syncthreads();

        float gt0[4], gt1[4];
        #pragma unroll
        for (int e = 0; e < 4; e++){
            int rb = (e*8 + jl) * 65;
            gt0[e] = ga0[e] + buf[rb + b0]        + buf[2080 + rb + b0]
                            + buf[4160 + rb + b0] + buf[6240 + rb + b0];
            gt1[e] = ga1[e] + buf[rb + b0+32]        + buf[2080 + rb + b0+32]
                            + buf[4160 + rb + b0+32] + buf[6240 + rb + b0+32];
        }
        // gate order: i, f, g, o
        c0 = sigf(gt0[1]) * c0 + sigf(gt0[0]) * tanhf(gt0[2]);
        float h0 = sigf(gt0[3]) * tanhf(c0);
        c1 = sigf(gt1[1]) * c1 + sigf(gt1[0]) * tanhf(gt1[2]);
        float h1 = sigf(gt1[3]) * tanhf(c1);

        const int pn = p ^ 1;
        float* hdst = g_h[pn][d];
        __stcg(hdst + (b0 << 9)        + j0 + jl, h0);
        __stcg(hdst + ((b0+32) << 9)   + j0 + jl, h1);

        if (layer == 0){
            float* sq = g_seq[d];
            sq[((size_t)t*64 + b0)      * HID + j0 + jl] = h0;
            sq[((size_t)t*64 + b0 + 32) * HID + j0 + jl] = h1;
        } else {
            out[(size_t)t*65536 + b0*1024        + (d << 9) + j0 + jl] = h0;
            out[(size_t)t*65536 + (b0+32)*1024   + (d << 9) + j0 + jl] = h1;
        }
        if (s == T_LEN - 1){
            const int row = d*2 + layer;           // [h_f l0, h_f l1, h_b l0, h_b l1]
            size_t hoff = OUT_ELEMS + (size_t)(row*64 + b0) * HID + j0 + jl;
            out[hoff]                           = h0;
            out[hoff + (32 << 9)]               = h1;
            out[hoff + HID_ELEMS]               = c0;
            out[hoff + HID_ELEMS + (32 << 9)]   = c1;
        }
        grid_barrier();
        p = pn;
    }
}

// ---------------------------------------------------------------------------
extern "C" void kernel_launch(void* const* d_in, const int* in_sizes, int n_in,
                              void* d_out, int out_size)
{
    const float* x     = (const float*)d_in[0];
    const float* Wxh_f = (const float*)d_in[1];
    const float* bxh_f = (const float*)d_in[2];
    const float* Whh_f = (const float*)d_in[3];
    const float* bhh_f = (const float*)d_in[4];
    const float* Wxh_b = (const float*)d_in[5];
    const float* bxh_b = (const float*)d_in[6];
    const float* Whh_b = (const float*)d_in[7];
    const float* bhh_b = (const float*)d_in[8];
    float* out = (float*)d_out;

    const int smem_bytes = (32 * WS + 64 * WS) * sizeof(float);   // 198144
    cudaFuncSetAttribute(recur_kernel,
                         cudaFuncAttributeMaxDynamicSharedMemorySize, smem_bytes);

    for (int l = 0; l < 2; l++){
        gemm_kernel<<<dim3(512, 16, 2), 256>>>(l, x, Wxh_f, Wxh_b,
                                               bxh_f, bhh_f, bxh_b, bhh_b);
        zero_h_kernel<<<512, 256>>>();
        recur_kernel<<<NBLK, 256, smem_bytes>>>(l, Whh_f, Whh_b, out);
    }
}

// round 4
// speedup vs baseline: 1.2058x; 1.2058x over previous
#include <cuda_runtime.h>
#include <cuda_bf16.h>
#include <math.h>
#include <cstdint>

#define T_LEN 1024
#define BATCH 64
#define HID   512
#define G4H   2048
#define NBLK  128
#define WS    516                      // padded smem row stride (conflict-free)
#define OUT_ELEMS 67108864LL           // T*B*2H
#define HID_ELEMS 131072LL             // 2L*B*H

// Scratch (allocation-free rule: __device__ globals)
__device__ float g_G[2][134217728];    // [d][T*B][4H]  precomputed x-part + biases
__device__ float g_seq[2][33554432];   // [d][T][B][H]  per-layer sequence output
__device__ float g_h[2][2][32768];     // [pingpong][d][B*H]
__device__ unsigned long long g_bar = 0ull;

__device__ __forceinline__ float sigf(float x){ return 1.0f / (1.0f + expf(-x)); }

// Monotonic-ticket grid barrier (known-good).
__device__ __forceinline__ void grid_barrier(){
    __threadfence();
    __syncthreads();
    if (threadIdx.x == 0){
        unsigned long long ticket = atomicAdd(&g_bar, 1ull);
        unsigned long long target = (ticket / NBLK + 1ull) * (unsigned long long)NBLK;
        while (atomicAdd(&g_bar, 0ull) < target) { __nanosleep(64); }
    }
    __syncthreads();
}

__global__ void zero_h_kernel(){
    int idx = blockIdx.x * blockDim.x + threadIdx.x;
    if (idx < 2*2*32768) ((float*)g_h)[idx] = 0.0f;
}

// ---------------------------------------------------------------------------
// mma.sync helpers (baseline PTX — compiles for generic compute_103)
// ---------------------------------------------------------------------------
__device__ __forceinline__ uint32_t smem_u32(const void* p){
    uint32_t a;
    asm("{ .reg .u64 t; cvta.to.shared.u64 t, %1; cvt.u32.u64 %0, t; }"
        : "=r"(a) : "l"(p));
    return a;
}

__device__ __forceinline__ void ldsm_x4(uint32_t* r, uint32_t addr){
    asm volatile("ldmatrix.sync.aligned.m8n8.x4.shared.b16 {%0,%1,%2,%3}, [%4];"
        : "=r"(r[0]), "=r"(r[1]), "=r"(r[2]), "=r"(r[3]) : "r"(addr));
}
__device__ __forceinline__ void ldsm_x2(uint32_t* r, uint32_t addr){
    asm volatile("ldmatrix.sync.aligned.m8n8.x2.shared.b16 {%0,%1}, [%2];"
        : "=r"(r[0]), "=r"(r[1]) : "r"(addr));
}
__device__ __forceinline__ void mma16816(float* c, const uint32_t* a, const uint32_t* b){
    asm volatile(
        "mma.sync.aligned.m16n8k16.row.col.f32.bf16.bf16.f32 "
        "{%0,%1,%2,%3}, {%4,%5,%6,%7}, {%8,%9}, {%0,%1,%2,%3};"
        : "+f"(c[0]), "+f"(c[1]), "+f"(c[2]), "+f"(c[3])
        : "r"(a[0]), "r"(a[1]), "r"(a[2]), "r"(a[3]), "r"(b[0]), "r"(b[1]));
}

// Split one float into (hi, lo) bf16 pair; pack two lanes into u32s.
__device__ __forceinline__ void split2(float x0, float x1, uint32_t &hi, uint32_t &lo){
    __nv_bfloat16 h0 = __float2bfloat16_rn(x0);
    __nv_bfloat16 h1 = __float2bfloat16_rn(x1);
    float r0 = x0 - __bfloat162float(h0);
    float r1 = x1 - __bfloat162float(h1);
    __nv_bfloat16 l0 = __float2bfloat16_rn(r0);
    __nv_bfloat16 l1 = __float2bfloat16_rn(r1);
    hi = ((uint32_t)__bfloat16_as_ushort(h1) << 16) | (uint32_t)__bfloat16_as_ushort(h0);
    lo = ((uint32_t)__bfloat16_as_ushort(l1) << 16) | (uint32_t)__bfloat16_as_ushort(l0);
}

// ---------------------------------------------------------------------------
// Input-projection GEMM on mma.sync bf16 (3-term split ~ fp32 accuracy).
// G[d][m][n] = X[m,:] . W[n,:] + bx[n] + bh[n]
// Block tile 128x128, K chunks of 32. Warp grid 2(M)x4(N), warp tile 64x32.
// SMEM per stage: A_hi/A_lo/B_hi/B_lo, 128 rows x 32 bf16, 80B padded rows
// (conflict-free for ldmatrix). Double-buffered via register prefetch.
// ---------------------------------------------------------------------------
#define STG_BYTES 40960               // 4 tiles * 128 rows * 80B
#define AHI_OFF   0
#define ALO_OFF   10240
#define BHI_OFF   20480
#define BLO_OFF   30720

__global__ void __launch_bounds__(256, 1)
gemm_mma_kernel(int layer, const float* __restrict__ x,
                const float* __restrict__ Wxf, const float* __restrict__ Wxb,
                const float* __restrict__ bxf, const float* __restrict__ bhf,
                const float* __restrict__ bxb, const float* __restrict__ bhb)
{
    extern __shared__ char smem[];
    float* bias_s = (float*)smem;                 // 128 floats
    char*  stage0 = smem + 1024;

    const int d  = blockIdx.z;
    const int n0 = blockIdx.x * 128;
    const int m0 = blockIdx.y * 128;
    const float* X  = (layer == 0) ? x : g_seq[d];
    const float* W  = (d ? Wxb : Wxf) + (size_t)layer * G4H * HID;
    const float* bx = (d ? bxb : bxf) + layer * G4H;
    const float* bh = (d ? bhb : bhf) + layer * G4H;
    float* Gout = g_G[d];

    const int tid  = threadIdx.x;
    const int wid  = tid >> 5;
    const int lane = tid & 31;
    const int warp_m = (wid >> 2) * 64;           // 0 or 64
    const int warp_n = (wid & 3) * 32;            // 0,32,64,96

    if (tid < 128) bias_s[tid] = bx[n0 + tid] + bh[n0 + tid];

    // per-lane ldmatrix row/seg selectors
    const int a_row_sel = (lane & 7) + ((lane >> 3) & 1) * 8;   // + mi*16
    const int a_kseg    = (lane >> 3) >> 1;                     // 0/1
    const int b_row_sel = lane & 7;                             // + ni*8
    const int b_kseg    = (lane >> 3) & 1;

    const uint32_t st_u32 = smem_u32(stage0);

    // staging indices: 4 iters, each thread loads one float4 of A and B
    int rrow[4], rf4[4];
    #pragma unroll
    for (int j = 0; j < 4; j++){
        int idx = tid + j * 256;
        rrow[j] = idx >> 3;
        rf4[j]  = idx & 7;
    }

    float acc[4][4][4];
    #pragma unroll
    for (int mi = 0; mi < 4; mi++)
        #pragma unroll
        for (int ni = 0; ni < 4; ni++)
            #pragma unroll
            for (int e = 0; e < 4; e++) acc[mi][ni][e] = 0.0f;

    float4 pa[4], pb[4];
    // prologue: load + stage chunk 0
    #pragma unroll
    for (int j = 0; j < 4; j++){
        pa[j] = *(const float4*)(X + (size_t)(m0 + rrow[j]) * HID + rf4[j] * 4);
        pb[j] = *(const float4*)(W + (size_t)(n0 + rrow[j]) * HID + rf4[j] * 4);
    }
    #pragma unroll
    for (int j = 0; j < 4; j++){
        uint32_t h0,l0,h1,l1;
        const int boff = rrow[j] * 80 + rf4[j] * 8;
        split2(pa[j].x, pa[j].y, h0, l0); split2(pa[j].z, pa[j].w, h1, l1);
        *(uint2*)(stage0 + AHI_OFF + boff) = make_uint2(h0, h1);
        *(uint2*)(stage0 + ALO_OFF + boff) = make_uint2(l0, l1);
        split2(pb[j].x, pb[j].y, h0, l0); split2(pb[j].z, pb[j].w, h1, l1);
        *(uint2*)(stage0 + BHI_OFF + boff) = make_uint2(h0, h1);
        *(uint2*)(stage0 + BLO_OFF + boff) = make_uint2(l0, l1);
    }
    __syncthreads();

    for (int c = 0; c < 16; c++){
        if (c < 15){
            const int kt = (c + 1) * 32;
            #pragma unroll
            for (int j = 0; j < 4; j++){
                pa[j] = *(const float4*)(X + (size_t)(m0 + rrow[j]) * HID + kt + rf4[j] * 4);
                pb[j] = *(const float4*)(W + (size_t)(n0 + rrow[j]) * HID + kt + rf4[j] * 4);
            }
        }

        const uint32_t sb = st_u32 + (uint32_t)(c & 1) * STG_BYTES;
        #pragma unroll
        for (int kk = 0; kk < 2; kk++){
            uint32_t ahi[4][4], alo[4][4], bhi[4][2], blo[4][2];
            #pragma unroll
            for (int mi = 0; mi < 4; mi++){
                const uint32_t ra = sb +
                    (uint32_t)((warp_m + mi*16 + a_row_sel) * 80 + (kk*2 + a_kseg) * 16);
                ldsm_x4(ahi[mi], ra + AHI_OFF);
                ldsm_x4(alo[mi], ra + ALO_OFF);
            }
            #pragma unroll
            for (int ni = 0; ni < 4; ni++){
                const uint32_t rb = sb +
                    (uint32_t)((warp_n + ni*8 + b_row_sel) * 80 + (kk*2 + b_kseg) * 16);
                ldsm_x2(bhi[ni], rb + BHI_OFF);
                ldsm_x2(blo[ni], rb + BLO_OFF);
            }
            #pragma unroll
            for (int mi = 0; mi < 4; mi++)
                #pragma unroll
                for (int ni = 0; ni < 4; ni++){
                    mma16816(acc[mi][ni], ahi[mi], bhi[ni]);
                    mma16816(acc[mi][ni], ahi[mi], blo[ni]);
                    mma16816(acc[mi][ni], alo[mi], bhi[ni]);
                }
        }

        if (c < 15){
            char* sp = stage0 + ((c + 1) & 1) * STG_BYTES;
            #pragma unroll
            for (int j = 0; j < 4; j++){
                uint32_t h0,l0,h1,l1;
                const int boff = rrow[j] * 80 + rf4[j] * 8;
                split2(pa[j].x, pa[j].y, h0, l0); split2(pa[j].z, pa[j].w, h1, l1);
                *(uint2*)(sp + AHI_OFF + boff) = make_uint2(h0, h1);
                *(uint2*)(sp + ALO_OFF + boff) = make_uint2(l0, l1);
                split2(pb[j].x, pb[j].y, h0, l0); split2(pb[j].z, pb[j].w, h1, l1);
                *(uint2*)(sp + BHI_OFF + boff) = make_uint2(h0, h1);
                *(uint2*)(sp + BLO_OFF + boff) = make_uint2(l0, l1);
            }
            __syncthreads();
        }
    }

    // Epilogue: direct STG (float2), bias added.
    #pragma unroll
    for (int mi = 0; mi < 4; mi++){
        const int r0 = m0 + warp_m + mi*16 + (lane >> 2);
        #pragma unroll
        for (int ni = 0; ni < 4; ni++){
            const int colL = warp_n + ni*8 + (lane & 3)*2;
            const float b0v = bias_s[colL], b1v = bias_s[colL + 1];
            const size_t o0 = (size_t)r0 * G4H + n0 + colL;
            *(float2*)(Gout + o0) =
                make_float2(acc[mi][ni][0] + b0v, acc[mi][ni][1] + b1v);
            *(float2*)(Gout + o0 + (size_t)8 * G4H) =
                make_float2(acc[mi][ni][2] + b0v, acc[mi][ni][3] + b1v);
        }
    }
}

// ---------------------------------------------------------------------------
// Persistent recurrent kernel (unchanged, known-good fp32 SIMT).
// ---------------------------------------------------------------------------
__global__ void __launch_bounds__(256, 1)
recur_kernel(int layer, const float* __restrict__ Whh_f,
             const float* __restrict__ Whh_b, float* __restrict__ out)
{
    extern __shared__ float sm[];
    float* w_s = sm;                 // 32 * WS
    float* h_s = sm + 32 * WS;       // 64 * WS
    float* buf = h_s;                // alias: 4*32*65 floats used after k-loop

    const int tid = threadIdx.x;
    const int bid = blockIdx.x;
    const int d  = bid >> 6;
    const int j0 = (bid & 63) << 3;
    const float* Wh = (d ? Whh_b : Whh_f) + (size_t)layer * G4H * HID;
    const float* Gm = g_G[d];

    for (int idx = tid; idx < 32 * 512; idx += 256){
        int rr = idx >> 9, k = idx & 511;
        int rg = ((rr >> 3) << 9) + j0 + (rr & 7);
        w_s[rr * WS + k] = Wh[(size_t)rg * HID + k];
    }

    const int kg = tid >> 6;
    const int q  = tid & 63;
    const int tc = q & 7;
    const int tr = q >> 3;
    const int kbase = kg << 7;

    const int jl = tid & 7;
    const int b0 = tid >> 3;
    float c0 = 0.0f, c1 = 0.0f;
    int p = 0;

    for (int s = 0; s < T_LEN; s++){
        const int t = d ? (T_LEN - 1 - s) : s;

        const float* hsrc = g_h[p][d];
        #pragma unroll
        for (int it = 0; it < 32; it++){
            int fi = (tid + it * 256) * 4;
            int b = fi >> 9, k = fi & 511;
            float4 v = __ldcg((const float4*)(hsrc + fi));
            *(float4*)&h_s[b * WS + k] = v;
        }
        const size_t mb0 = ((size_t)t * 64 + b0)      * G4H + j0 + jl;
        const size_t mb1 = ((size_t)t * 64 + b0 + 32) * G4H + j0 + jl;
        float ga0[4], ga1[4];
        #pragma unroll
        for (int e = 0; e < 4; e++){
            ga0[e] = __ldg(Gm + mb0 + (e << 9));
            ga1[e] = __ldg(Gm + mb1 + (e << 9));
        }
        __syncthreads();

        float acc[4][8];
        #pragma unroll
        for (int i = 0; i < 4; i++)
            #pragma unroll
            for (int u = 0; u < 8; u++) acc[i][u] = 0.0f;

        #pragma unroll 4
        for (int kq = 0; kq < 32; kq++){
            const int k = kbase + (kq << 2);
            float4 wv[4], hv[8];
            #pragma unroll
            for (int i = 0; i < 4; i++)
                wv[i] = *(const float4*)&w_s[(i*8 + tr) * WS + k];
            #pragma unroll
            for (int u = 0; u < 8; u++)
                hv[u] = *(const float4*)&h_s[(tc + (u << 3)) * WS + k];
            #pragma unroll
            for (int i = 0; i < 4; i++)
                #pragma unroll
                for (int u = 0; u < 8; u++){
                    acc[i][u] += wv[i].x * hv[u].x;
                    acc[i][u] += wv[i].y * hv[u].y;
                    acc[i][u] += wv[i].z * hv[u].z;
                    acc[i][u] += wv[i].w * hv[u].w;
                }
        }
        __syncthreads();

        #pragma unroll
        for (int i = 0; i < 4; i++)
            #pragma unroll
            for (int u = 0; u < 8; u++)
                buf[(kg*32 + i*8 + tr) * 65 + tc + (u << 3)] = acc[i][u];
        __syncthreads();

        float gt0[4], gt1[4];
        #pragma unroll
        for (int e = 0; e < 4; e++){
            int rb = (e*8 + jl) * 65;
            gt0[e] = ga0[e] + buf[rb + b0]        + buf[2080 + rb + b0]
                            + buf[4160 + rb + b0] + buf[6240 + rb + b0];
            gt1[e] = ga1[e] + buf[rb + b0+32]        + buf[2080 + rb + b0+32]
                            + buf[4160 + rb + b0+32] + buf[6240 + rb + b0+32];
        }
        c0 = sigf(gt0[1]) * c0 + sigf(gt0[0]) * tanhf(gt0[2]);
        float h0 = sigf(gt0[3]) * tanhf(c0);
        c1 = sigf(gt1[1]) * c1 + sigf(gt1[0]) * tanhf(gt1[2]);
        float h1 = sigf(gt1[3]) * tanhf(c1);

        const int pn = p ^ 1;
        float* hdst = g_h[pn][d];
        __stcg(hdst + (b0 << 9)        + j0 + jl, h0);
        __stcg(hdst + ((b0+32) << 9)   + j0 + jl, h1);

        if (layer == 0){
            float* sq = g_seq[d];
            sq[((size_t)t*64 + b0)      * HID + j0 + jl] = h0;
            sq[((size_t)t*64 + b0 + 32) * HID + j0 + jl] = h1;
        } else {
            out[(size_t)t*65536 + b0*1024        + (d << 9) + j0 + jl] = h0;
            out[(size_t)t*65536 + (b0+32)*1024   + (d << 9) + j0 + jl] = h1;
        }
        if (s == T_LEN - 1){
            const int row = d*2 + layer;
            size_t hoff = OUT_ELEMS + (size_t)(row*64 + b0) * HID + j0 + jl;
            out[hoff]                           = h0;
            out[hoff + (32 << 9)]               = h1;
            out[hoff + HID_ELEMS]               = c0;
            out[hoff + HID_ELEMS + (32 << 9)]   = c1;
        }
        grid_barrier();
        p = pn;
    }
}

// ---------------------------------------------------------------------------
extern "C" void kernel_launch(void* const* d_in, const int* in_sizes, int n_in,
                              void* d_out, int out_size)
{
    const float* x     = (const float*)d_in[0];
    const float* Wxh_f = (const float*)d_in[1];
    const float* bxh_f = (const float*)d_in[2];
    const float* Whh_f = (const float*)d_in[3];
    const float* bhh_f = (const float*)d_in[4];
    const float* Wxh_b = (const float*)d_in[5];
    const float* bxh_b = (const float*)d_in[6];
    const float* Whh_b = (const float*)d_in[7];
    const float* bhh_b = (const float*)d_in[8];
    float* out = (float*)d_out;

    const int gemm_smem = 1024 + 2 * STG_BYTES;                   // 82944 B
    cudaFuncSetAttribute(gemm_mma_kernel,
                         cudaFuncAttributeMaxDynamicSharedMemorySize, gemm_smem);
    const int rec_smem = (32 * WS + 64 * WS) * sizeof(float);     // 198144
    cudaFuncSetAttribute(recur_kernel,
                         cudaFuncAttributeMaxDynamicSharedMemorySize, rec_smem);

    for (int l = 0; l < 2; l++){
        gemm_mma_kernel<<<dim3(16, 512, 2), 256, gemm_smem>>>(l, x, Wxh_f, Wxh_b,
                                                              bxh_f, bhh_f, bxh_b, bhh_b);
        zero_h_kernel<<<512, 256>>>();
        recur_kernel<<<NBLK, 256, rec_smem>>>(l, Whh_f, Whh_b, out);
    }
}

// round 5
// speedup vs baseline: 1.7938x; 1.4877x over previous
#include <cuda_runtime.h>
#include <cuda_bf16.h>
#include <math.h>
#include <cstdint>

#define T_LEN 1024
#define BATCH 64
#define HID   512
#define G4H   2048
#define OUT_ELEMS 67108864LL           // T*B*2H
#define HID_ELEMS 131072LL             // 2L*B*H

// Scratch (allocation-free rule: __device__ globals)
__device__ float g_G[2][134217728];    // [d][T*B][4H]  precomputed x-part + biases
__device__ float g_seq[2][33554432];   // [d][T][B][H]  per-layer sequence output
__device__ __nv_bfloat16 g_h_hi[2][2][32768];  // [pingpong][d][B*H] bf16-hi plane
__device__ __nv_bfloat16 g_h_lo[2][2][32768];  // [pingpong][d][B*H] bf16-lo plane
__device__ unsigned long long g_bar2[2] = {0ull, 0ull};

__device__ __forceinline__ float sigf(float x){ return 1.0f / (1.0f + expf(-x)); }

// Per-direction monotonic-ticket barrier over 64 blocks.
__device__ __forceinline__ void grid_barrier_dir(int d){
    __threadfence();
    __syncthreads();
    if (threadIdx.x == 0){
        unsigned long long ticket = atomicAdd(&g_bar2[d], 1ull);
        unsigned long long target = (ticket / 64ull + 1ull) * 64ull;
        while (atomicAdd(&g_bar2[d], 0ull) < target) { __nanosleep(32); }
    }
    __syncthreads();
}

__global__ void zero_h_kernel(){
    int idx = blockIdx.x * blockDim.x + threadIdx.x;   // 131072 threads
    if (idx < 65536){
        ((uint32_t*)g_h_hi)[idx] = 0u;
        ((uint32_t*)g_h_lo)[idx] = 0u;
    }
}

// ---------------------------------------------------------------------------
// mma.sync helpers (baseline PTX — compiles for generic compute_103)
// ---------------------------------------------------------------------------
__device__ __forceinline__ uint32_t smem_u32(const void* p){
    uint32_t a;
    asm("{ .reg .u64 t; cvta.to.shared.u64 t, %1; cvt.u32.u64 %0, t; }"
        : "=r"(a) : "l"(p));
    return a;
}
__device__ __forceinline__ void ldsm_x4(uint32_t* r, uint32_t addr){
    asm volatile("ldmatrix.sync.aligned.m8n8.x4.shared.b16 {%0,%1,%2,%3}, [%4];"
        : "=r"(r[0]), "=r"(r[1]), "=r"(r[2]), "=r"(r[3]) : "r"(addr));
}
__device__ __forceinline__ void ldsm_x2(uint32_t* r, uint32_t addr){
    asm volatile("ldmatrix.sync.aligned.m8n8.x2.shared.b16 {%0,%1}, [%2];"
        : "=r"(r[0]), "=r"(r[1]) : "r"(addr));
}
__device__ __forceinline__ void mma16816(float* c, const uint32_t* a, const uint32_t* b){
    asm volatile(
        "mma.sync.aligned.m16n8k16.row.col.f32.bf16.bf16.f32 "
        "{%0,%1,%2,%3}, {%4,%5,%6,%7}, {%8,%9}, {%0,%1,%2,%3};"
        : "+f"(c[0]), "+f"(c[1]), "+f"(c[2]), "+f"(c[3])
        : "r"(a[0]), "r"(a[1]), "r"(a[2]), "r"(a[3]), "r"(b[0]), "r"(b[1]));
}

// Split one float into (hi, lo) bf16 pair; pack two lanes into u32s.
__device__ __forceinline__ void split2(float x0, float x1, uint32_t &hi, uint32_t &lo){
    __nv_bfloat16 h0 = __float2bfloat16_rn(x0);
    __nv_bfloat16 h1 = __float2bfloat16_rn(x1);
    float r0 = x0 - __bfloat162float(h0);
    float r1 = x1 - __bfloat162float(h1);
    __nv_bfloat16 l0 = __float2bfloat16_rn(r0);
    __nv_bfloat16 l1 = __float2bfloat16_rn(r1);
    hi = ((uint32_t)__bfloat16_as_ushort(h1) << 16) | (uint32_t)__bfloat16_as_ushort(h0);
    lo = ((uint32_t)__bfloat16_as_ushort(l1) << 16) | (uint32_t)__bfloat16_as_ushort(l0);
}

// ---------------------------------------------------------------------------
// Input-projection GEMM on mma.sync bf16 (3-term split) — unchanged from R4.
// ---------------------------------------------------------------------------
#define STG_BYTES 40960               // 4 tiles * 128 rows * 80B
#define AHI_OFF   0
#define ALO_OFF   10240
#define BHI_OFF   20480
#define BLO_OFF   30720

__global__ void __launch_bounds__(256, 1)
gemm_mma_kernel(int layer, const float* __restrict__ x,
                const float* __restrict__ Wxf, const float* __restrict__ Wxb,
                const float* __restrict__ bxf, const float* __restrict__ bhf,
                const float* __restrict__ bxb, const float* __restrict__ bhb)
{
    extern __shared__ char smem[];
    float* bias_s = (float*)smem;                 // 128 floats
    char*  stage0 = smem + 1024;

    const int d  = blockIdx.z;
    const int n0 = blockIdx.x * 128;
    const int m0 = blockIdx.y * 128;
    const float* X  = (layer == 0) ? x : g_seq[d];
    const float* W  = (d ? Wxb : Wxf) + (size_t)layer * G4H * HID;
    const float* bx = (d ? bxb : bxf) + layer * G4H;
    const float* bh = (d ? bhb : bhf) + layer * G4H;
    float* Gout = g_G[d];

    const int tid  = threadIdx.x;
    const int wid  = tid >> 5;
    const int lane = tid & 31;
    const int warp_m = (wid >> 2) * 64;
    const int warp_n = (wid & 3) * 32;

    if (tid < 128) bias_s[tid] = bx[n0 + tid] + bh[n0 + tid];

    const int a_row_sel = (lane & 7) + ((lane >> 3) & 1) * 8;
    const int a_kseg    = (lane >> 3) >> 1;
    const int b_row_sel = lane & 7;
    const int b_kseg    = (lane >> 3) & 1;

    const uint32_t st_u32 = smem_u32(stage0);

    int rrow[4], rf4[4];
    #pragma unroll
    for (int j = 0; j < 4; j++){
        int idx = tid + j * 256;
        rrow[j] = idx >> 3;
        rf4[j]  = idx & 7;
    }

    float acc[4][4][4];
    #pragma unroll
    for (int mi = 0; mi < 4; mi++)
        #pragma unroll
        for (int ni = 0; ni < 4; ni++)
            #pragma unroll
            for (int e = 0; e < 4; e++) acc[mi][ni][e] = 0.0f;

    float4 pa[4], pb[4];
    #pragma unroll
    for (int j = 0; j < 4; j++){
        pa[j] = *(const float4*)(X + (size_t)(m0 + rrow[j]) * HID + rf4[j] * 4);
        pb[j] = *(const float4*)(W + (size_t)(n0 + rrow[j]) * HID + rf4[j] * 4);
    }
    #pragma unroll
    for (int j = 0; j < 4; j++){
        uint32_t h0,l0,h1,l1;
        const int boff = rrow[j] * 80 + rf4[j] * 8;
        split2(pa[j].x, pa[j].y, h0, l0); split2(pa[j].z, pa[j].w, h1, l1);
        *(uint2*)(stage0 + AHI_OFF + boff) = make_uint2(h0, h1);
        *(uint2*)(stage0 + ALO_OFF + boff) = make_uint2(l0, l1);
        split2(pb[j].x, pb[j].y, h0, l0); split2(pb[j].z, pb[j].w, h1, l1);
        *(uint2*)(stage0 + BHI_OFF + boff) = make_uint2(h0, h1);
        *(uint2*)(stage0 + BLO_OFF + boff) = make_uint2(l0, l1);
    }
    __syncthreads();

    for (int c = 0; c < 16; c++){
        if (c < 15){
            const int kt = (c + 1) * 32;
            #pragma unroll
            for (int j = 0; j < 4; j++){
                pa[j] = *(const float4*)(X + (size_t)(m0 + rrow[j]) * HID + kt + rf4[j] * 4);
                pb[j] = *(const float4*)(W + (size_t)(n0 + rrow[j]) * HID + kt + rf4[j] * 4);
            }
        }

        const uint32_t sb = st_u32 + (uint32_t)(c & 1) * STG_BYTES;
        #pragma unroll
        for (int kk = 0; kk < 2; kk++){
            uint32_t ahi[4][4], alo[4][4], bhi[4][2], blo[4][2];
            #pragma unroll
            for (int mi = 0; mi < 4; mi++){
                const uint32_t ra = sb +
                    (uint32_t)((warp_m + mi*16 + a_row_sel) * 80 + (kk*2 + a_kseg) * 16);
                ldsm_x4(ahi[mi], ra + AHI_OFF);
                ldsm_x4(alo[mi], ra + ALO_OFF);
            }
            #pragma unroll
            for (int ni = 0; ni < 4; ni++){
                const uint32_t rb = sb +
                    (uint32_t)((warp_n + ni*8 + b_row_sel) * 80 + (kk*2 + b_kseg) * 16);
                ldsm_x2(bhi[ni], rb + BHI_OFF);
                ldsm_x2(blo[ni], rb + BLO_OFF);
            }
            #pragma unroll
            for (int mi = 0; mi < 4; mi++)
                #pragma unroll
                for (int ni = 0; ni < 4; ni++){
                    mma16816(acc[mi][ni], ahi[mi], bhi[ni]);
                    mma16816(acc[mi][ni], ahi[mi], blo[ni]);
                    mma16816(acc[mi][ni], alo[mi], bhi[ni]);
                }
        }

        if (c < 15){
            char* sp = stage0 + ((c + 1) & 1) * STG_BYTES;
            #pragma unroll
            for (int j = 0; j < 4; j++){
                uint32_t h0,l0,h1,l1;
                const int boff = rrow[j] * 80 + rf4[j] * 8;
                split2(pa[j].x, pa[j].y, h0, l0); split2(pa[j].z, pa[j].w, h1, l1);
                *(uint2*)(sp + AHI_OFF + boff) = make_uint2(h0, h1);
                *(uint2*)(sp + ALO_OFF + boff) = make_uint2(l0, l1);
                split2(pb[j].x, pb[j].y, h0, l0); split2(pb[j].z, pb[j].w, h1, l1);
                *(uint2*)(sp + BHI_OFF + boff) = make_uint2(h0, h1);
                *(uint2*)(sp + BLO_OFF + boff) = make_uint2(l0, l1);
            }
            __syncthreads();
        }
    }

    #pragma unroll
    for (int mi = 0; mi < 4; mi++){
        const int r0 = m0 + warp_m + mi*16 + (lane >> 2);
        #pragma unroll
        for (int ni = 0; ni < 4; ni++){
            const int colL = warp_n + ni*8 + (lane & 3)*2;
            const float b0v = bias_s[colL], b1v = bias_s[colL + 1];
            const size_t o0 = (size_t)r0 * G4H + n0 + colL;
            *(float2*)(Gout + o0) =
                make_float2(acc[mi][ni][0] + b0v, acc[mi][ni][1] + b1v);
            *(float2*)(Gout + o0 + (size_t)8 * G4H) =
                make_float2(acc[mi][ni][2] + b0v, acc[mi][ni][3] + b1v);
        }
    }
}

// ---------------------------------------------------------------------------
// Persistent recurrent kernel on mma.sync bf16 (3-term split).
// Block = (direction, 8 hidden units) -> 32 gate rows (N), 64 batch (M), K=512.
// SMEM: W hi/lo planes [32 x 1040B], h hi/lo planes [64 x 1040B].
// 8 warps: 4 (M, 16 batch each) x 2 (N, 16 gate rows each).
// ---------------------------------------------------------------------------
#define WROW    1040
#define WHI_OFF 0
#define WLO_OFF 33280
#define HHI_OFF 66560
#define HLO_OFF 133120
#define REC_SMEM 199680

__global__ void __launch_bounds__(256, 1)
recur_kernel(int layer, const float* __restrict__ Whh_f,
             const float* __restrict__ Whh_b, float* __restrict__ out)
{
    extern __shared__ char smem[];
    float* buf = (float*)(smem + HHI_OFF);   // alias: 32x65 floats, used post-MMA

    const int tid = threadIdx.x;
    const int bid = blockIdx.x;
    const int d  = bid >> 6;
    const int j0 = (bid & 63) << 3;
    const float* Wh = (d ? Whh_b : Whh_f) + (size_t)layer * G4H * HID;
    const float* Gm = g_G[d];

    // Pre-split W slice into bf16 hi/lo smem planes (once per launch).
    for (int idx = tid; idx < 32 * 512; idx += 256){
        int rr = idx >> 9, k = idx & 511;
        int rg = ((rr >> 3) << 9) + j0 + (rr & 7);     // gate*512 + j0 + jl
        float w = Wh[(size_t)rg * HID + k];
        __nv_bfloat16 hi = __float2bfloat16_rn(w);
        __nv_bfloat16 lo = __float2bfloat16_rn(w - __bfloat162float(hi));
        *(__nv_bfloat16*)(smem + WHI_OFF + rr * WROW + k * 2) = hi;
        *(__nv_bfloat16*)(smem + WLO_OFF + rr * WROW + k * 2) = lo;
    }

    const int wid  = tid >> 5;
    const int lane = tid & 31;
    const int warp_m = (wid & 3) * 16;       // batch offset
    const int warp_n = (wid >> 2) * 16;      // gate-row offset
    const int a_row = (lane & 7) + ((lane >> 3) & 1) * 8;
    const int a_ks  = lane >> 4;
    const int b_row = lane & 7;
    const int b_ks  = (lane >> 3) & 1;

    const uint32_t s32 = smem_u32(smem);
    const uint32_t a_hi_b = s32 + HHI_OFF + (uint32_t)(warp_m + a_row) * WROW + a_ks * 16;
    const uint32_t a_lo_b = s32 + HLO_OFF + (uint32_t)(warp_m + a_row) * WROW + a_ks * 16;
    const uint32_t b_hi_b = s32 + WHI_OFF + (uint32_t)(warp_n + b_row) * WROW + b_ks * 16;
    const uint32_t b_lo_b = s32 + WLO_OFF + (uint32_t)(warp_n + b_row) * WROW + b_ks * 16;

    const int jl = tid & 7;
    const int b0 = tid >> 3;
    float c0 = 0.0f, c1 = 0.0f;
    int p = 0;

    for (int s = 0; s < T_LEN; s++){
        const int t = d ? (T_LEN - 1 - s) : s;

        // Stage h hi/lo planes (L2-resident, written by peer SMs last step).
        const __nv_bfloat16* hh = g_h_hi[p][d];
        const __nv_bfloat16* hl = g_h_lo[p][d];
        #pragma unroll
        for (int it = 0; it < 16; it++){
            int idx = tid + it * 256;                       // 0..4095 uint4s
            uint32_t so = (uint32_t)(idx >> 6) * WROW + (uint32_t)(idx & 63) * 16;
            uint4 vh = __ldcg((const uint4*)hh + idx);
            uint4 vl = __ldcg((const uint4*)hl + idx);
            *(uint4*)(smem + HHI_OFF + so) = vh;
            *(uint4*)(smem + HLO_OFF + so) = vl;
        }
        // G prefetch (hides DRAM latency behind the MMA loop)
        const size_t mb0 = ((size_t)t * 64 + b0)      * G4H + j0 + jl;
        const size_t mb1 = ((size_t)t * 64 + b0 + 32) * G4H + j0 + jl;
        float ga0[4], ga1[4];
        #pragma unroll
        for (int e = 0; e < 4; e++){
            ga0[e] = __ldg(Gm + mb0 + (e << 9));
            ga1[e] = __ldg(Gm + mb1 + (e << 9));
        }
        __syncthreads();

        float acc[2][4];
        #pragma unroll
        for (int ni = 0; ni < 2; ni++)
            #pragma unroll
            for (int e = 0; e < 4; e++) acc[ni][e] = 0.0f;

        #pragma unroll 4
        for (int ck = 0; ck < 32; ck++){
            const uint32_t off = (uint32_t)ck * 32;
            uint32_t ah[4], al[4], bh[2][2], bl[2][2];
            ldsm_x4(ah, a_hi_b + off);
            ldsm_x4(al, a_lo_b + off);
            ldsm_x2(bh[0], b_hi_b + off);
            ldsm_x2(bh[1], b_hi_b + off + 8 * WROW);
            ldsm_x2(bl[0], b_lo_b + off);
            ldsm_x2(bl[1], b_lo_b + off + 8 * WROW);
            // pass-major ordering breaks acc dependency chains
            mma16816(acc[0], ah, bh[0]);
            mma16816(acc[1], ah, bh[1]);
            mma16816(acc[0], ah, bl[0]);
            mma16816(acc[1], ah, bl[1]);
            mma16816(acc[0], al, bh[0]);
            mma16816(acc[1], al, bh[1]);
        }
        __syncthreads();   // all h-plane reads done before buf alias writes

        // Fragment -> buf[gate_row][batch] exchange.
        const int er = warp_m + (lane >> 2);
        #pragma unroll
        for (int ni = 0; ni < 2; ni++){
            const int bc = warp_n + ni * 8 + (lane & 3) * 2;
            buf[bc * 65 + er]           = acc[ni][0];
            buf[(bc + 1) * 65 + er]     = acc[ni][1];
            buf[bc * 65 + er + 8]       = acc[ni][2];
            buf[(bc + 1) * 65 + er + 8] = acc[ni][3];
        }
        __syncthreads();

        float gt0[4], gt1[4];
        #pragma unroll
        for (int e = 0; e < 4; e++){
            const int rb = (e * 8 + jl) * 65;
            gt0[e] = ga0[e] + buf[rb + b0];
            gt1[e] = ga1[e] + buf[rb + b0 + 32];
        }
        // gate order: i, f, g, o
        c0 = sigf(gt0[1]) * c0 + sigf(gt0[0]) * tanhf(gt0[2]);
        float h0 = sigf(gt0[3]) * tanhf(c0);
        c1 = sigf(gt1[1]) * c1 + sigf(gt1[0]) * tanhf(gt1[2]);
        float h1 = sigf(gt1[3]) * tanhf(c1);

        // Write next-step h planes (bf16 hi/lo, split at source).
        const int pn = p ^ 1;
        {
            __nv_bfloat16 h0h = __float2bfloat16_rn(h0);
            __nv_bfloat16 h0l = __float2bfloat16_rn(h0 - __bfloat162float(h0h));
            __nv_bfloat16 h1h = __float2bfloat16_rn(h1);
            __nv_bfloat16 h1l = __float2bfloat16_rn(h1 - __bfloat162float(h1h));
            const int i0 = (b0 << 9) + j0 + jl;
            const int i1 = ((b0 + 32) << 9) + j0 + jl;
            g_h_hi[pn][d][i0] = h0h;  g_h_lo[pn][d][i0] = h0l;
            g_h_hi[pn][d][i1] = h1h;  g_h_lo[pn][d][i1] = h1l;
        }

        if (layer == 0){
            float* sq = g_seq[d];
            sq[((size_t)t*64 + b0)      * HID + j0 + jl] = h0;
            sq[((size_t)t*64 + b0 + 32) * HID + j0 + jl] = h1;
        } else {
            out[(size_t)t*65536 + b0*1024        + (d << 9) + j0 + jl] = h0;
            out[(size_t)t*65536 + (b0+32)*1024   + (d << 9) + j0 + jl] = h1;
        }
        if (s == T_LEN - 1){
            const int row = d*2 + layer;
            size_t hoff = OUT_ELEMS + (size_t)(row*64 + b0) * HID + j0 + jl;
            out[hoff]                           = h0;
            out[hoff + (32 << 9)]               = h1;
            out[hoff + HID_ELEMS]               = c0;
            out[hoff + HID_ELEMS + (32 << 9)]   = c1;
        }
        grid_barrier_dir(d);
        p = pn;
    }
}

// ---------------------------------------------------------------------------
extern "C" void kernel_launch(void* const* d_in, const int* in_sizes, int n_in,
                              void* d_out, int out_size)
{
    const float* x     = (const float*)d_in[0];
    const float* Wxh_f = (const float*)d_in[1];
    const float* bxh_f = (const float*)d_in[2];
    const float* Whh_f = (const float*)d_in[3];
    const float* bhh_f = (const float*)d_in[4];
    const float* Wxh_b = (const float*)d_in[5];
    const float* bxh_b = (const float*)d_in[6];
    const float* Whh_b = (const float*)d_in[7];
    const float* bhh_b = (const float*)d_in[8];
    float* out = (float*)d_out;

    const int gemm_smem = 1024 + 2 * STG_BYTES;                   // 82944 B
    cudaFuncSetAttribute(gemm_mma_kernel,
                         cudaFuncAttributeMaxDynamicSharedMemorySize, gemm_smem);
    cudaFuncSetAttribute(recur_kernel,
                         cudaFuncAttributeMaxDynamicSharedMemorySize, REC_SMEM);

    for (int l = 0; l < 2; l++){
        gemm_mma_kernel<<<dim3(16, 512, 2), 256, gemm_smem>>>(l, x, Wxh_f, Wxh_b,
                                                              bxh_f, bhh_f, bxh_b, bhh_b);
        zero_h_kernel<<<512, 256>>>();
        recur_kernel<<<128, 256, REC_SMEM>>>(l, Whh_f, Whh_b, out);
    }
}